// round 3
// baseline (speedup 1.0000x reference)
#include <cuda_runtime.h>
#include <math.h>

typedef unsigned long long u64;

#define Bsz 2
#define Lsz 2048
#define Hsz 16
#define Dsz 64
#define HIDsz 1024
#define NPOS (Bsz*Lsz)        // 4096
#define NO 128                // 2*D
#define BR_ROW0 1792          // branch region start row in W1

// ---------------- static device scratch (no allocation allowed) -------------
__device__ float g_Hc[NPOS * NO];                      // 2 MB hidden-segment GEMM out
__device__ float g_wsum[12 * NO];                      // stat-block column sums
__device__ __align__(16) u64 g_W1T_hid[512 * NO];      // hidden W1, k-pair packed, [kp][o]
__device__ __align__(16) u64 g_W1bT[128 * 132];        // branch W1, r-pair packed, [r2][o pad132]

// ---------------- packed fp32 helpers ---------------------------------------
__device__ __forceinline__ u64 ffma2(u64 a, u64 b, u64 c) {
    u64 d; asm("fma.rn.f32x2 %0, %1, %2, %3;" : "=l"(d) : "l"(a), "l"(b), "l"(c)); return d;
}
__device__ __forceinline__ u64 pack2(float x, float y) {
    u64 r; asm("mov.b64 %0, {%1, %2};" : "=l"(r) : "f"(x), "f"(y)); return r;
}
__device__ __forceinline__ float lo2(u64 v) { return __int_as_float((int)(unsigned)v); }
__device__ __forceinline__ float hi2(u64 v) { return __int_as_float((int)(v >> 32)); }
__device__ __forceinline__ float gelu_exact(float x) {
    return 0.5f * x * (1.f + erff(x * 0.70710678118654752f));
}

// ---------------------------------------------------------------------------
// Prep: transposed/packed W1 tables + stat column sums
// ---------------------------------------------------------------------------
__global__ void __launch_bounds__(256) k_prep(const float* __restrict__ W1) {
    int idx = blockIdx.x * 256 + threadIdx.x;
    if (idx < 65536) {                       // hidden region: [kp][o]
        int kp = idx >> 7, o = idx & 127;
        g_W1T_hid[kp * NO + o] =
            pack2(W1[(2 * kp) * NO + o], W1[(2 * kp + 1) * NO + o]);
    } else if (idx < 81920) {                // branch region: [r2][o pad 132]
        int t = idx - 65536;
        int r2 = t >> 7, o = t & 127;
        g_W1bT[r2 * 132 + o] =
            pack2(W1[(BR_ROW0 + 2 * r2) * NO + o], W1[(BR_ROW0 + 2 * r2 + 1) * NO + o]);
    } else if (idx < 83456) {                // wsum
        int t = idx - 81920;
        int s = t >> 7, o = t & 127;
        const float* p = W1 + (HIDsz + s * Dsz) * NO + o;
        float acc = 0.f;
#pragma unroll
        for (int r = 0; r < Dsz; r++) acc += p[r * NO];
        g_wsum[t] = acc;
    }
}

// ---------------------------------------------------------------------------
// Hidden GEMM: Hc[pos][o] = hidden[pos,:] @ W1[0:1024,:]  (FFMA2, k-parity)
// Block = 16 positions, 8 warps, warp-K-split (64 k-pairs each), m=16 reuse.
// W reads coalesced from L2-resident [kp][o] table.
// ---------------------------------------------------------------------------
__global__ void __launch_bounds__(256) k_hidden(const float* __restrict__ hid) {
    extern __shared__ float sph[];           // 8 warps * 16 m * 128 o = 64 KB
    int tid = threadIdx.x, w = tid >> 5, lane = tid & 31;
    int pos0 = blockIdx.x * 16;

    u64 acc[16][4];
#pragma unroll
    for (int m = 0; m < 16; m++)
#pragma unroll
        for (int j = 0; j < 4; j++) acc[m][j] = 0ull;

    const u64* WT = g_W1T_hid;
    int kb = w * 64;

#pragma unroll 2
    for (int i = 0; i < 64; i++) {
        int kp = kb + i;
        const u64* wr = WT + kp * NO;
        u64 wv0 = wr[lane];
        u64 wv1 = wr[lane + 32];
        u64 wv2 = wr[lane + 64];
        u64 wv3 = wr[lane + 96];
#pragma unroll
        for (int m = 0; m < 16; m++) {
            u64 h2 = *(const u64*)(hid + (size_t)(pos0 + m) * HIDsz + 2 * kp);
            acc[m][0] = ffma2(h2, wv0, acc[m][0]);
            acc[m][1] = ffma2(h2, wv1, acc[m][1]);
            acc[m][2] = ffma2(h2, wv2, acc[m][2]);
            acc[m][3] = ffma2(h2, wv3, acc[m][3]);
        }
    }

    float* spw = sph + w * 2048;
#pragma unroll
    for (int m = 0; m < 16; m++) {
        spw[m * 128 + lane]      = lo2(acc[m][0]) + hi2(acc[m][0]);
        spw[m * 128 + lane + 32] = lo2(acc[m][1]) + hi2(acc[m][1]);
        spw[m * 128 + lane + 64] = lo2(acc[m][2]) + hi2(acc[m][2]);
        spw[m * 128 + lane + 96] = lo2(acc[m][3]) + hi2(acc[m][3]);
    }
    __syncthreads();

#pragma unroll
    for (int k = 0; k < 8; k++) {
        int u = tid + k * 256;               // u = m*128 + o
        float s = 0.f;
#pragma unroll
        for (int wi = 0; wi < 8; wi++) s += sph[wi * 2048 + u];
        g_Hc[pos0 * NO + u] = s;
    }
}

// ---------------------------------------------------------------------------
// Main kernel: branch GEMM fragment (FFMA2, r-parity, 16 heads/warp)
// + stat correction + gelu + W2 + softmax/temp/floor/renorm epilogue.
// Block = 8 positions (8 warps). W1bT staged once in smem ([r2][o pad132],
// conflict-free wv reads).
// ---------------------------------------------------------------------------
#define T2_U64 (128 * 132)                   // 16896
#define XS_U64 (8 * 32 * 17)                 // 4352 (per-warp [32 r2][16 h pad17])
#define SMF    (1024 + 1536 + 1536 + 512 + 128 + 64 + 16 + 4)   // 4820 floats
#define SMEM_MAIN_BYTES ((T2_U64 + XS_U64) * 8 + SMF * 4)       // 189264

__global__ void __launch_bounds__(256) k_main(
    const float* __restrict__ br0, const float* __restrict__ br1,
    const float* __restrict__ br2, const float* __restrict__ br3,
    const float* __restrict__ bias1, const float* __restrict__ W2,
    const float* __restrict__ bias2, const float* __restrict__ epsf,
    const float* __restrict__ temp, float* __restrict__ out)
{
    extern __shared__ u64 smu[];
    u64* sT2 = smu;                          // 16896 u64
    u64* xs2 = smu + T2_U64;                 // 4352 u64
    float* smf  = (float*)(smu + T2_U64 + XS_U64);
    float* sHc  = smf;                       // 1024
    float* sws  = smf + 1024;                // 1536
    float* sst  = smf + 2560;                // 1536
    float* sW2  = smf + 4096;                // 512
    float* sb1  = smf + 4608;                // 128
    float* seps = smf + 4736;                // 64
    float* stp  = smf + 4800;                // 16
    float* sb2  = smf + 4816;                // 4

    int tid = threadIdx.x, w = tid >> 5, lane = tid & 31;
    int pos0 = blockIdx.x * 8;

    {   // cooperative smem fills
        float4* d4 = (float4*)sT2;
        const float4* s4 = (const float4*)g_W1bT;
        for (int i = tid; i < 8448; i += 256) d4[i] = s4[i];
        ((float4*)sHc)[tid] = ((const float4*)(g_Hc + pos0 * NO))[tid];
        if (tid < 128) {
            ((float4*)sws)[tid]       = ((const float4*)g_wsum)[tid];
            ((float4*)sws)[tid + 128] = ((const float4*)g_wsum)[tid + 128];
            ((float4*)sws)[tid + 256] = ((const float4*)g_wsum)[tid + 256];
            ((float4*)sW2)[tid] = ((const float4*)W2)[tid];
            sb1[tid] = bias1[tid];
        }
        if (tid < 64) seps[tid] = epsf[tid];
        if (tid < 16) stp[tid] = temp[tid];
        if (tid < 4)  sb2[tid] = bias2[tid];
    }
    __syncthreads();

    const float* brs[4] = { br0, br1, br2, br3 };
    int pos = pos0 + w;
    u64*   xw   = xs2 + w * 544;             // [32 r2][pad 17]
    float* sstw = sst + w * 192;

    u64 acc[16][4];
#pragma unroll
    for (int q = 0; q < 16; q++)
#pragma unroll
        for (int j = 0; j < 4; j++) acc[q][j] = 0ull;

    for (int b = 0; b < 4; b++) {
        // ---- stage branch chunk (16 heads x 64 vals) + stats ----
        // store layout: xw[r2=lane][h]  (pad 17 -> 2-way STS conflict only)
        const float2* bp = (const float2*)brs[b] + (size_t)(pos * Hsz) * 32;
#pragma unroll
        for (int h = 0; h < 16; h++) {
            float2 v = bp[h * 32 + lane];
            xw[lane * 17 + h] = pack2(v.x, v.y);
            float s  = v.x + v.y;
            float qd = v.x * v.x + v.y * v.y;
            float mx = fmaxf(v.x, v.y);
#pragma unroll
            for (int off = 16; off; off >>= 1) {
                s  += __shfl_xor_sync(0xffffffffu, s,  off);
                qd += __shfl_xor_sync(0xffffffffu, qd, off);
                mx  = fmaxf(mx, __shfl_xor_sync(0xffffffffu, mx, off));
            }
            if (lane == 0) {
                sstw[h * 12 + 3 * b + 0] = s * (1.f / 64.f);
                sstw[h * 12 + 3 * b + 1] = sqrtf(fmaxf(qd * (1.f / 64.f), 1e-8f));
                sstw[h * 12 + 3 * b + 2] = mx;
            }
        }
        __syncwarp();

        // ---- packed FMA loop over this branch's 32 r-pairs ----
        int cb = b * 32;
#pragma unroll 2
        for (int i = 0; i < 32; i++) {
            const u64* wr = sT2 + (cb + i) * 132;
            u64 wv0 = wr[lane];              // conflict-free: consecutive u64
            u64 wv1 = wr[lane + 32];
            u64 wv2 = wr[lane + 64];
            u64 wv3 = wr[lane + 96];
            const u64* xr = xw + i * 17;     // broadcast reads
#pragma unroll
            for (int q = 0; q < 16; q++) {
                u64 xq = xr[q];
                acc[q][0] = ffma2(xq, wv0, acc[q][0]);
                acc[q][1] = ffma2(xq, wv1, acc[q][1]);
                acc[q][2] = ffma2(xq, wv2, acc[q][2]);
                acc[q][3] = ffma2(xq, wv3, acc[q][3]);
            }
        }
        __syncwarp();
    }

    // ---- epilogue ----
    float base[4];
#pragma unroll
    for (int j = 0; j < 4; j++)
        base[j] = sHc[w * 128 + lane + 32 * j] + sb1[lane + 32 * j];
    float4 r0 = ((const float4*)sW2)[lane];
    float4 r1 = ((const float4*)sW2)[lane + 32];
    float4 r2 = ((const float4*)sW2)[lane + 64];
    float4 r3 = ((const float4*)sW2)[lane + 96];

#pragma unroll
    for (int q = 0; q < 16; q++) {
        float a0 = lo2(acc[q][0]) + hi2(acc[q][0]) + base[0];
        float a1 = lo2(acc[q][1]) + hi2(acc[q][1]) + base[1];
        float a2 = lo2(acc[q][2]) + hi2(acc[q][2]) + base[2];
        float a3 = lo2(acc[q][3]) + hi2(acc[q][3]) + base[3];
#pragma unroll
        for (int s = 0; s < 12; s++) {
            float st = sstw[q * 12 + s];
            a0 += st * sws[s * 128 + lane];
            a1 += st * sws[s * 128 + lane + 32];
            a2 += st * sws[s * 128 + lane + 64];
            a3 += st * sws[s * 128 + lane + 96];
        }
        float g0 = gelu_exact(a0), g1 = gelu_exact(a1);
        float g2 = gelu_exact(a2), g3 = gelu_exact(a3);
        float lpx = g0*r0.x + g1*r1.x + g2*r2.x + g3*r3.x;
        float lpy = g0*r0.y + g1*r1.y + g2*r2.y + g3*r3.y;
        float lpz = g0*r0.z + g1*r1.z + g2*r2.z + g3*r3.z;
        float lpw = g0*r0.w + g1*r1.w + g2*r2.w + g3*r3.w;
#pragma unroll
        for (int off = 16; off; off >>= 1) {
            lpx += __shfl_xor_sync(0xffffffffu, lpx, off);
            lpy += __shfl_xor_sync(0xffffffffu, lpy, off);
            lpz += __shfl_xor_sync(0xffffffffu, lpz, off);
            lpw += __shfl_xor_sync(0xffffffffu, lpw, off);
        }
        if (lane == 0) {
            float t  = fminf(fmaxf(stp[q], 0.2f), 10.f);
            float it = 1.f / t;
            float l0 = (lpx + sb2[0]) * it;
            float l1 = (lpy + sb2[1]) * it;
            float l2 = (lpz + sb2[2]) * it;
            float l3 = (lpw + sb2[3]) * it;
            float mx = fmaxf(fmaxf(l0, l1), fmaxf(l2, l3));
            float e0 = expf(l0 - mx), e1 = expf(l1 - mx);
            float e2 = expf(l2 - mx), e3 = expf(l3 - mx);
            float is = 1.f / (e0 + e1 + e2 + e3);
            float w0 = e0 * is, w1 = e1 * is, w2 = e2 * is, w3 = e3 * is;
            w0 = fmaxf(w0, fminf(fmaxf(seps[q*4+0], 1e-7f), 0.1f));
            w1 = fmaxf(w1, fminf(fmaxf(seps[q*4+1], 1e-7f), 0.1f));
            w2 = fmaxf(w2, fminf(fmaxf(seps[q*4+2], 1e-7f), 0.1f));
            w3 = fmaxf(w3, fminf(fmaxf(seps[q*4+3], 1e-7f), 0.1f));
            float inv = 1.f / (w0 + w1 + w2 + w3);
            ((float4*)out)[pos * Hsz + q] =
                make_float4(w0 * inv, w1 * inv, w2 * inv, w3 * inv);
        }
    }
}

// ---------------------------------------------------------------------------
extern "C" void kernel_launch(void* const* d_in, const int* in_sizes, int n_in,
                              void* d_out, int out_size)
{
    const float* hidden = (const float*)d_in[0];
    const float* br0    = (const float*)d_in[1];
    const float* br1    = (const float*)d_in[2];
    const float* br2    = (const float*)d_in[3];
    const float* br3    = (const float*)d_in[4];
    const float* W1     = (const float*)d_in[5];
    const float* bias1  = (const float*)d_in[6];
    const float* W2     = (const float*)d_in[7];
    const float* bias2  = (const float*)d_in[8];
    const float* epsf   = (const float*)d_in[9];
    const float* temp   = (const float*)d_in[10];

    cudaFuncSetAttribute(k_hidden, cudaFuncAttributeMaxDynamicSharedMemorySize, 65536);
    cudaFuncSetAttribute(k_main, cudaFuncAttributeMaxDynamicSharedMemorySize, SMEM_MAIN_BYTES);

    k_prep<<<326, 256>>>(W1);
    k_hidden<<<NPOS / 16, 256, 65536>>>(hidden);
    k_main<<<NPOS / 8, 256, SMEM_MAIN_BYTES>>>(br0, br1, br2, br3, bias1, W2, bias2,
                                               epsf, temp, (float*)d_out);
}

// round 5
// speedup vs baseline: 2.1181x; 2.1181x over previous
#include <cuda_runtime.h>
#include <math.h>
#include <stdint.h>

#define NPOS 4096
#define NO 128
#define HIDsz 1024
#define BR_ROW0 1792

// ---------------- static device scratch (no allocation allowed) -------------
__device__ float g_Hc[NPOS * NO];                       // hidden GEMM out (fp32 exact)
__device__ __align__(16) float g_Bfrag[34 * 16 * 64];   // B in mma fragment order [ki][nt][lane][2]

// ---------------- helpers ----------------------------------------------------
__device__ __forceinline__ float tf32r(float x) {       // round-to-nearest tf32
    uint32_t r; asm("cvt.rna.tf32.f32 %0, %1;" : "=r"(r) : "f"(x));
    return __uint_as_float(r);
}
__device__ __forceinline__ float gelu_exact(float x) {
    return 0.5f * x * (1.f + erff(x * 0.70710678118654752f));
}
__device__ __forceinline__ void mma_tf32(float* d, uint32_t a0, uint32_t a1,
                                         uint32_t a2, uint32_t a3,
                                         uint32_t b0, uint32_t b1) {
    asm("mma.sync.aligned.m16n8k8.row.col.f32.tf32.tf32.f32 "
        "{%0,%1,%2,%3}, {%4,%5,%6,%7}, {%8,%9}, {%0,%1,%2,%3};"
        : "+f"(d[0]), "+f"(d[1]), "+f"(d[2]), "+f"(d[3])
        : "r"(a0), "r"(a1), "r"(a2), "r"(a3), "r"(b0), "r"(b1));
}

// ---------------------------------------------------------------------------
// Prep: B in fragment order, tf32-rounded.
// Element idx -> i = idx&1, lane = (idx>>1)&31, nt = (idx>>6)&15, ki = idx>>10.
// k = ki*8 + lane%4 + 4*i ; n = nt*8 + lane/4.
// k<256: W1 branch rows; 256..267: stat colsums; 268: b1; else 0.
// ---------------------------------------------------------------------------
__global__ void __launch_bounds__(256) k_prep(const float* __restrict__ W1,
                                              const float* __restrict__ b1) {
    int idx = blockIdx.x * 256 + threadIdx.x;
    if (idx >= 34 * 16 * 64) return;
    int i = idx & 1, lane = (idx >> 1) & 31, nt = (idx >> 6) & 15, ki = idx >> 10;
    int k = ki * 8 + (lane & 3) + 4 * i;
    int n = nt * 8 + (lane >> 2);
    float v;
    if (k < 256) {
        v = W1[(BR_ROW0 + k) * NO + n];
    } else {
        int ks = k - 256;
        if (ks < 12) {
            const float* p = W1 + (HIDsz + ks * 64) * NO + n;
            float a = 0.f;
#pragma unroll
            for (int r = 0; r < 64; r++) a += p[r * NO];
            v = a;
        } else if (ks == 12) v = b1[n];
        else v = 0.f;
    }
    g_Bfrag[idx] = tf32r(v);
}

// ---------------------------------------------------------------------------
// Hidden GEMM (exact fp32, known-good R1): Hc = hidden @ W1[0:1024,:]
// ---------------------------------------------------------------------------
__global__ void __launch_bounds__(256) k_hidden(const float* __restrict__ hid,
                                                const float* __restrict__ W1) {
    __shared__ float4 Hcp[8][8][32];
    int tid = threadIdx.x, w = tid >> 5, lane = tid & 31;
    int pos0 = blockIdx.x * 8;

    float4 acc[8];
#pragma unroll
    for (int m = 0; m < 8; m++) acc[m] = make_float4(0.f, 0.f, 0.f, 0.f);

    const float4* W4 = (const float4*)W1;
    int kbase = w * 128;
#pragma unroll 4
    for (int kk = 0; kk < 128; kk++) {
        int k = kbase + kk;
        float4 wv = W4[k * 32 + lane];
#pragma unroll
        for (int m = 0; m < 8; m++) {
            float hv = hid[(pos0 + m) * HIDsz + k];
            acc[m].x += hv * wv.x; acc[m].y += hv * wv.y;
            acc[m].z += hv * wv.z; acc[m].w += hv * wv.w;
        }
    }
#pragma unroll
    for (int m = 0; m < 8; m++) Hcp[w][m][lane] = acc[m];
    __syncthreads();

    int m = tid >> 5, ol = tid & 31;
    float4 s = make_float4(0.f, 0.f, 0.f, 0.f);
#pragma unroll
    for (int wi = 0; wi < 8; wi++) {
        float4 v = Hcp[wi][m][ol];
        s.x += v.x; s.y += v.y; s.z += v.z; s.w += v.w;
    }
    ((float4*)g_Hc)[(pos0 + m) * 32 + ol] = s;
}

// ---------------------------------------------------------------------------
// Main: mma.sync tf32 GEMM (M=128 = 8 pos x 16 heads, N=128, K=272)
// + in-staging stats + fused epilogue. 1 warp = 1 position.
// ---------------------------------------------------------------------------
#define SM_B   0
#define SM_A   34816                 // 8 warps * 1056 floats (8 ki * 132)
#define SM_HC  (SM_A + 8448)
#define SM_ST  (SM_HC + 1024)        // 8 warps * 16 rows * 12
#define SM_W2  (SM_ST + 1536)
#define SM_EPS (SM_W2 + 512)
#define SM_TP  (SM_EPS + 64)
#define SM_B2  (SM_TP + 16)
#define SM_TOT (SM_B2 + 4)
#define SMEM_MAIN_BYTES (SM_TOT * 4)  // 185,680 B

__global__ void __launch_bounds__(256) k_main(
    const float* __restrict__ br0, const float* __restrict__ br1,
    const float* __restrict__ br2, const float* __restrict__ br3,
    const float* __restrict__ W2,  const float* __restrict__ b2,
    const float* __restrict__ epsf, const float* __restrict__ temp,
    float* __restrict__ out)
{
    extern __shared__ float sm[];
    float* sB   = sm + SM_B;
    float* sA   = sm + SM_A;
    float* sHc  = sm + SM_HC;
    float* sst  = sm + SM_ST;
    float* sW2  = sm + SM_W2;
    float* seps = sm + SM_EPS;
    float* stp  = sm + SM_TP;
    float* sb2  = sm + SM_B2;

    int tid = threadIdx.x, w = tid >> 5, L = tid & 31;
    int pos0 = blockIdx.x * 8;

    {   // cooperative fills
        float4* d4 = (float4*)sB;
        const float4* s4 = (const float4*)g_Bfrag;
        for (int i = tid; i < 8704; i += 256) d4[i] = s4[i];
        ((float4*)sHc)[tid] = ((const float4*)(g_Hc + pos0 * NO))[tid];
        if (tid < 128) ((float4*)sW2)[tid] = ((const float4*)W2)[tid];
        if (tid < 64) seps[tid] = epsf[tid];
        if (tid < 16) stp[tid] = temp[tid];
        if (tid < 4)  sb2[tid] = b2[tid];
    }
    __syncthreads();

    const float* brs[4] = { br0, br1, br2, br3 };
    float* sAw  = sA + w * 1056;
    float* sstw = sst + w * 192;
    const uint2* bfp = (const uint2*)sB;

    float acc[16][4];
#pragma unroll
    for (int nt = 0; nt < 16; nt++)
#pragma unroll
        for (int j = 0; j < 4; j++) acc[nt][j] = 0.f;

    int rbase = L >> 4;            // 0 or 1
    int q16   = L & 15;
    int kiw   = q16 >> 1;          // ki this thread writes
    int regh  = (q16 & 1) * 2;     // reg offset (c-half)

#pragma unroll
    for (int b = 0; b < 4; b++) {
        // ---- stage branch chunk into A-frag layout + compute stats ----
        const float4* src = (const float4*)(brs[b] + (size_t)(pos0 + w) * 1024);
#pragma unroll
        for (int j = 0; j < 8; j++) {
            float4 v = src[L + 32 * j];
            int r = rbase + 2 * j;
            float s  = v.x + v.y + v.z + v.w;
            float qd = v.x*v.x + v.y*v.y + v.z*v.z + v.w*v.w;
            float mx = fmaxf(fmaxf(v.x, v.y), fmaxf(v.z, v.w));
#pragma unroll
            for (int off = 1; off <= 8; off <<= 1) {
                s  += __shfl_xor_sync(0xffffffffu, s,  off);
                qd += __shfl_xor_sync(0xffffffffu, qd, off);
                mx  = fmaxf(mx, __shfl_xor_sync(0xffffffffu, mx, off));
            }
            if (q16 == 0) {
                sstw[r * 12 + 3 * b + 0] = s * (1.f / 64.f);
                sstw[r * 12 + 3 * b + 1] = sqrtf(fmaxf(qd * (1.f / 64.f), 1e-8f));
                sstw[r * 12 + 3 * b + 2] = mx;
            }
            int base = kiw * 132 + (r & 7) * 16 + (r >> 3) + regh;
            sAw[base + 0]  = tf32r(v.x);
            sAw[base + 4]  = tf32r(v.y);
            sAw[base + 8]  = tf32r(v.z);
            sAw[base + 12] = tf32r(v.w);
        }
        __syncwarp();

        // ---- 8 k-iters x 16 n-tiles of m16n8k8 tf32 mma ----
        for (int ki = 0; ki < 8; ki++) {
            uint4 af = *(const uint4*)(sAw + ki * 132 + L * 4);
            int kib = b * 8 + ki;
#pragma unroll
            for (int nt = 0; nt < 16; nt++) {
                uint2 bv = bfp[kib * 512 + nt * 32 + L];
                mma_tf32(acc[nt], af.x, af.y, af.z, af.w, bv.x, bv.y);
            }
        }
        __syncwarp();   // A buffer reused by next branch
    }

    // ---- stats k-iters (ki 32,33): A frags computed from sst ----
    {
        int r0 = L >> 2, cl = L & 3;
#pragma unroll
        for (int kk = 0; kk < 2; kk++) {
            uint32_t a[4];
#pragma unroll
            for (int u = 0; u < 4; u++) {
                int r = (u & 1) ? r0 + 8 : r0;
                int c = kk * 8 + cl + ((u >> 1) ? 4 : 0);
                float v;
                if (c < 12)       v = tf32r(sstw[r * 12 + c]);
                else if (c == 12) v = 1.0f;
                else              v = 0.0f;
                a[u] = __float_as_uint(v);
            }
            int kib = 32 + kk;
#pragma unroll
            for (int nt = 0; nt < 16; nt++) {
                uint2 bv = bfp[kib * 512 + nt * 32 + L];
                mma_tf32(acc[nt], a[0], a[1], a[2], a[3], bv.x, bv.y);
            }
        }
    }

    // ---- epilogue: gelu -> W2 -> quad-reduce -> softmax/temp/floor/renorm ----
    {
        int cl = L & 3, r0 = L >> 2;
        const float* hcw = sHc + w * 128;
        const float4* w24 = (const float4*)sW2;
        float l0[4] = {0.f, 0.f, 0.f, 0.f};
        float l1[4] = {0.f, 0.f, 0.f, 0.f};
#pragma unroll
        for (int nt = 0; nt < 16; nt++) {
            int o0 = nt * 8 + cl * 2;
            float g00 = gelu_exact(acc[nt][0] + hcw[o0]);
            float g01 = gelu_exact(acc[nt][1] + hcw[o0 + 1]);
            float g10 = gelu_exact(acc[nt][2] + hcw[o0]);
            float g11 = gelu_exact(acc[nt][3] + hcw[o0 + 1]);
            float4 wa = w24[o0], wb = w24[o0 + 1];
            l0[0] += g00 * wa.x + g01 * wb.x;
            l0[1] += g00 * wa.y + g01 * wb.y;
            l0[2] += g00 * wa.z + g01 * wb.z;
            l0[3] += g00 * wa.w + g01 * wb.w;
            l1[0] += g10 * wa.x + g11 * wb.x;
            l1[1] += g10 * wa.y + g11 * wb.y;
            l1[2] += g10 * wa.z + g11 * wb.z;
            l1[3] += g10 * wa.w + g11 * wb.w;
        }
#pragma unroll
        for (int off = 1; off <= 2; off <<= 1) {
#pragma unroll
            for (int j = 0; j < 4; j++) {
                l0[j] += __shfl_xor_sync(0xffffffffu, l0[j], off);
                l1[j] += __shfl_xor_sync(0xffffffffu, l1[j], off);
            }
        }
        if (cl == 0) {
            int pos = pos0 + w;
            float4* outp = ((float4*)out) + pos * 16;
#pragma unroll
            for (int half = 0; half < 2; half++) {
                float* l = half ? l1 : l0;
                int h = r0 + half * 8;
                float t  = fminf(fmaxf(stp[h], 0.2f), 10.f);
                float it = 1.f / t;
                float v0 = (l[0] + sb2[0]) * it;
                float v1 = (l[1] + sb2[1]) * it;
                float v2 = (l[2] + sb2[2]) * it;
                float v3 = (l[3] + sb2[3]) * it;
                float mx = fmaxf(fmaxf(v0, v1), fmaxf(v2, v3));
                float e0 = expf(v0 - mx), e1 = expf(v1 - mx);
                float e2 = expf(v2 - mx), e3 = expf(v3 - mx);
                float is = 1.f / (e0 + e1 + e2 + e3);
                float w0 = e0 * is, w1 = e1 * is, w2v = e2 * is, w3 = e3 * is;
                w0  = fmaxf(w0,  fminf(fmaxf(seps[h*4+0], 1e-7f), 0.1f));
                w1  = fmaxf(w1,  fminf(fmaxf(seps[h*4+1], 1e-7f), 0.1f));
                w2v = fmaxf(w2v, fminf(fmaxf(seps[h*4+2], 1e-7f), 0.1f));
                w3  = fmaxf(w3,  fminf(fmaxf(seps[h*4+3], 1e-7f), 0.1f));
                float inv = 1.f / (w0 + w1 + w2v + w3);
                outp[h] = make_float4(w0 * inv, w1 * inv, w2v * inv, w3 * inv);
            }
        }
    }
}

// ---------------------------------------------------------------------------
extern "C" void kernel_launch(void* const* d_in, const int* in_sizes, int n_in,
                              void* d_out, int out_size)
{
    const float* hidden = (const float*)d_in[0];
    const float* br0    = (const float*)d_in[1];
    const float* br1    = (const float*)d_in[2];
    const float* br2    = (const float*)d_in[3];
    const float* br3    = (const float*)d_in[4];
    const float* W1     = (const float*)d_in[5];
    const float* bias1  = (const float*)d_in[6];
    const float* W2     = (const float*)d_in[7];
    const float* bias2  = (const float*)d_in[8];
    const float* epsf   = (const float*)d_in[9];
    const float* temp   = (const float*)d_in[10];

    cudaFuncSetAttribute(k_main, cudaFuncAttributeMaxDynamicSharedMemorySize, SMEM_MAIN_BYTES);

    k_prep<<<136, 256>>>(W1, bias1);
    k_hidden<<<NPOS / 8, 256>>>(hidden, W1);
    k_main<<<NPOS / 8, 256, SMEM_MAIN_BYTES>>>(br0, br1, br2, br3, W2, bias2,
                                               epsf, temp, (float*)d_out);
}